// round 15
// baseline (speedup 1.0000x reference)
#include <cuda_runtime.h>
#include <cuda_fp16.h>
#include <math.h>
#include <stdint.h>

// ===========================================================================
// LogicRecursiveNN on GB300 (plain sm_103 target -> mma.sync path).
// Single-pass fp16 GEMMs, f32 accumulate.
// ALGEBRAIC OPTS:
//  - L1-G1 factored through the 2000-entry dictionary: PQ = emb @ [w1t|w1b].
//  - L1-G2 FUSES the H = relu(P[ia]+Q[ib]+b1) construction into its A-tile
//    loader (LDG from L2-resident PQ -> f32 add -> relu -> STS), so the
//    134 MB H buffer never touches DRAM.
//  - Head: th batch-constant -> th @ h1_top folded into bias.
// Hot GEMMs: 128x128 CTA, 128 thr, warp tile 64x64, KC=32, 4 stg, 2 CTAs/SM.
// Tail GEMMs (< 1 wave): split-K (S<=8) + reduce.
// ===========================================================================

#define B_    512
#define NT_   2
#define NL_   64
#define E_    512
#define T_    512

#define SB_   ((size_t)B_ * NT_ * NL_ * E_ / 2)
#define SH_   ((size_t)B_ * NT_ * (NL_/2) * 4 * E_)
#define SZ1_  ((size_t)B_ * E_)
#define SZ2_  ((size_t)B_ * (E_/2))
#define SZ3_  ((size_t)B_ * (E_/4))
#define NENT_ 2000
#define NENTP 2048

__device__ __half g_bufA[SB_];
__device__ __half g_bufB[SB_];
__device__ __half g_bufH[SH_];
__device__ __half g_z1[SZ1_];
__device__ __half g_z2[SZ2_];
__device__ __half g_z3[SZ3_];
__device__ __half g_wT[6193152];
__device__ __half g_wPQT[(size_t)4096 * 512];
__device__ __half g_emb16[(size_t)NENTP * E_];
__device__ __half g_PQ[(size_t)NENTP * 4096];
__device__ __half g_b1h[2048];
__device__ float  g_skP[8388608];
__device__ float  g_zeroBias[4096];
__device__ float  g_hb1p[E_];

#define W1T_OFF  0          // [2048,1024]
#define W2T_OFF  2097152    // [512,2048]
#define O1T_OFF  3145728    // [2048,512]
#define O2T_OFF  4194304    // [512,2048]
#define H1T_OFF  5242880    // [512,1024]  (h1 bottom only)
#define H2T_OFF  6029312    // [256,512]
#define H3T_OFF  6160384    // [128,256]

// ---------------------------------------------------------------------------
// helpers
// ---------------------------------------------------------------------------
__device__ __forceinline__ uint32_t smem_u32(const void* p) {
    uint32_t a;
    asm("{ .reg .u64 t; cvta.to.shared.u64 t, %1; cvt.u32.u64 %0, t; }"
        : "=r"(a) : "l"(p));
    return a;
}
__device__ __forceinline__ void cp16(uint32_t dst, const void* src) {
    asm volatile("cp.async.cg.shared.global [%0], [%1], 16;"
                 :: "r"(dst), "l"(src) : "memory");
}
__device__ __forceinline__ void cp_commit() {
    asm volatile("cp.async.commit_group;" ::: "memory");
}
template <int N>
__device__ __forceinline__ void cp_wait() {
    asm volatile("cp.async.wait_group %0;" :: "n"(N) : "memory");
}
__device__ __forceinline__ void ldm_x4(uint32_t* r, uint32_t addr) {
    asm volatile("ldmatrix.sync.aligned.m8n8.x4.shared.b16 {%0,%1,%2,%3}, [%4];"
                 : "=r"(r[0]), "=r"(r[1]), "=r"(r[2]), "=r"(r[3]) : "r"(addr));
}
__device__ __forceinline__ void mma_f16(float* c, const uint32_t* a, const uint32_t* b) {
    asm volatile(
        "mma.sync.aligned.m16n8k16.row.col.f32.f16.f16.f32 "
        "{%0,%1,%2,%3}, {%4,%5,%6,%7}, {%8,%9}, {%0,%1,%2,%3};"
        : "+f"(c[0]), "+f"(c[1]), "+f"(c[2]), "+f"(c[3])
        : "r"(a[0]), "r"(a[1]), "r"(a[2]), "r"(a[3]), "r"(b[0]), "r"(b[1]));
}

#define ACT_RELU 0
#define ACT_TANH 1
#define ACT_NONE 2
template <int ACT>
__device__ __forceinline__ float apply_act(float x) {
    if (ACT == ACT_RELU) return fmaxf(x, 0.0f);
    if (ACT == ACT_TANH) return tanhf(x);
    return x;
}

// ---------------------------------------------------------------------------
// small kernels
// ---------------------------------------------------------------------------
__global__ void emb_cvt_kernel(const float* __restrict__ emb,
                               __half* __restrict__ out)
{
    const size_t o = (size_t)blockIdx.x * E_ + threadIdx.x * 4;
    const float4 v = *(const float4*)(emb + o);
    __half h[4];
    h[0] = __float2half_rn(v.x); h[1] = __float2half_rn(v.y);
    h[2] = __float2half_rn(v.z); h[3] = __float2half_rn(v.w);
    *(uint2*)(out + o) = *(uint2*)h;
}

__global__ void b1_cvt_kernel(const float* __restrict__ b1,
                              __half* __restrict__ out)
{
    const int i = blockIdx.x * blockDim.x + threadIdx.x;
    out[i] = __float2half_rn(b1[i]);
}

struct TransJobs {
    const float* W[9];
    __half* Wt[9];
    int K[9], N[9];
    int ofs[10];
};

__global__ void transpose_all(TransJobs jobs)
{
    __shared__ float t[32][33];
    int j = 0;
#pragma unroll
    for (int q = 1; q < 9; q++) if ((int)blockIdx.x >= jobs.ofs[q]) j = q;
    const int tile = blockIdx.x - jobs.ofs[j];
    const int K = jobs.K[j], N = jobs.N[j];
    const int tilesX = N / 32;
    const int bx = (tile % tilesX) * 32;
    const int by = (tile / tilesX) * 32;
    const float* W = jobs.W[j];
    __half* Wt = jobs.Wt[j];

    for (int i = threadIdx.y; i < 32; i += 8)
        t[i][threadIdx.x] = W[(size_t)(by + i) * N + bx + threadIdx.x];
    __syncthreads();
    for (int i = threadIdx.y; i < 32; i += 8)
        Wt[(size_t)(bx + i) * K + by + threadIdx.x] = __float2half_rn(t[threadIdx.x][i]);
}

// hb1'[n] = hb1[n] + sum_t th[t] * h1[t, n]
__global__ void headbias_kernel(const float* __restrict__ th,
                                const float* __restrict__ h1,
                                const float* __restrict__ hb1,
                                float* __restrict__ outb)
{
    const int n = blockIdx.x * blockDim.x + threadIdx.x;
    float s = hb1[n];
    for (int t = 0; t < T_; t++)
        s = fmaf(th[t], h1[(size_t)t * E_ + n], s);
    outb[n] = s;
}

__global__ void final_kernel(const __half* __restrict__ z3,
                             const float* __restrict__ w,
                             const float* __restrict__ b0,
                             float* __restrict__ out)
{
    const int warp = (blockIdx.x * blockDim.x + threadIdx.x) >> 5;
    const int lane = threadIdx.x & 31;
    if (warp >= B_) return;
    const size_t base = (size_t)warp * 128;
    float s = 0.0f;
#pragma unroll
    for (int i = lane; i < 128; i += 32)
        s = fmaf(__half2float(z3[base + i]), w[i], s);
#pragma unroll
    for (int o = 16; o > 0; o >>= 1) s += __shfl_down_sync(0xFFFFFFFFu, s, o);
    if (lane == 0) {
        const float x = s + b0[0];
        out[warp] = 1.0f / (1.0f + expf(-x));
    }
}

// ---------------------------------------------------------------------------
// GEMM tiling constants
// ---------------------------------------------------------------------------
#define KC       32
#define PITCH    80
#define STG4     4
#define TILE128  (128 * PITCH)
#define STAGE128 (2 * TILE128)
#define GSMEM128 (STG4 * STAGE128)           // 81920 (x2 CTAs = 160 KB/SM)

// ---------------------------------------------------------------------------
// gemm_mma: full-K kernel, bias+act epilogue, fp16 out.
// ---------------------------------------------------------------------------
template <int ACT>
__global__ void __launch_bounds__(128, 2)
gemm_mma(const __half* __restrict__ A,
         const __half* __restrict__ Bt,
         const float* __restrict__ bias,
         __half* __restrict__ C,
         int M, int N, int K)
{
    extern __shared__ char smem[];
    const uint32_t sb = smem_u32(smem);
    const int tid = threadIdx.x;
    const int wid = tid >> 5;
    const int lane = tid & 31;
    const int wm = wid >> 1;
    const int wn = wid & 1;

    const size_t row0 = (size_t)blockIdx.y * 128;
    const size_t col0 = (size_t)blockIdx.x * 128;
    const __half* Ag = A + row0 * K;
    const __half* Bg = Bt + col0 * K;

    const int seg = tid & 3;
    const int rowc = tid >> 2;

    const int nk = K / KC;

#pragma unroll
    for (int c = 0; c < STG4 - 1; c++) {
        if (c < nk) {
            const uint32_t st = sb + c * STAGE128;
            const int k0 = c * KC;
#pragma unroll
            for (int h = 0; h < 4; h++) {
                const int r = rowc + h * 32;
                const size_t go = (size_t)r * K + k0 + seg * 8;
                const uint32_t so = r * PITCH + seg * 16;
                cp16(st + so, Ag + go);
                cp16(st + TILE128 + so, Bg + go);
            }
        }
        cp_commit();
    }

    float acc[4][8][4];
#pragma unroll
    for (int i = 0; i < 4; i++)
#pragma unroll
        for (int j = 0; j < 8; j++)
#pragma unroll
            for (int k = 0; k < 4; k++) acc[i][j][k] = 0.0f;

    const uint32_t aoff = (uint32_t)((wm * 64 + (lane & 15)) * PITCH + (lane >> 4) * 16);
    const uint32_t boff = (uint32_t)((wn * 64 + (lane & 7) + ((lane >> 4) << 3)) * PITCH
                                     + ((lane >> 3) & 1) * 16);

    for (int i = 0; i < nk; i++) {
        cp_wait<STG4 - 2>();
        __syncthreads();

        const uint32_t st = sb + (i % STG4) * STAGE128;
        const uint32_t aB = st + aoff;
        const uint32_t bB = st + TILE128 + boff;

        uint32_t af[2][4][4], bf[2][4][4];
#pragma unroll
        for (int ks = 0; ks < 2; ks++) {
#pragma unroll
            for (int mt = 0; mt < 4; mt++)
                ldm_x4(af[ks][mt], aB + mt * (16 * PITCH) + ks * 32);
#pragma unroll
            for (int nt2 = 0; nt2 < 4; nt2++)
                ldm_x4(bf[ks][nt2], bB + nt2 * (16 * PITCH) + ks * 32);
        }
#pragma unroll
        for (int ks = 0; ks < 2; ks++)
#pragma unroll
            for (int mt = 0; mt < 4; mt++)
#pragma unroll
                for (int nt2 = 0; nt2 < 4; nt2++) {
                    mma_f16(acc[mt][2 * nt2 + 0], af[ks][mt], &bf[ks][nt2][0]);
                    mma_f16(acc[mt][2 * nt2 + 1], af[ks][mt], &bf[ks][nt2][2]);
                }

        const int c = i + STG4 - 1;
        if (c < nk) {
            const uint32_t stw = sb + (c % STG4) * STAGE128;
            const int k0 = c * KC;
#pragma unroll
            for (int h = 0; h < 4; h++) {
                const int r = rowc + h * 32;
                const size_t go = (size_t)r * K + k0 + seg * 8;
                const uint32_t so = r * PITCH + seg * 16;
                cp16(stw + so, Ag + go);
                cp16(stw + TILE128 + so, Bg + go);
            }
        }
        cp_commit();
    }

    const int lr = lane >> 2;
    const int lc = (lane & 3) * 2;
#pragma unroll
    for (int mt = 0; mt < 4; mt++) {
#pragma unroll
        for (int nt = 0; nt < 8; nt++) {
            const size_t r0 = row0 + wm * 64 + mt * 16 + lr;
            const size_t cc = col0 + wn * 64 + nt * 8 + lc;
            const float bx = __ldg(bias + cc);
            const float by = __ldg(bias + cc + 1);
#pragma unroll
            for (int hh = 0; hh < 2; hh++) {
                const size_t r = r0 + hh * 8;
                __half hp[2];
                hp[0] = __float2half_rn(apply_act<ACT>(acc[mt][nt][hh * 2 + 0] + bx));
                hp[1] = __float2half_rn(apply_act<ACT>(acc[mt][nt][hh * 2 + 1] + by));
                *(uint32_t*)(C + r * N + cc) = *(uint32_t*)hp;
            }
        }
    }
}

// ---------------------------------------------------------------------------
// gemm_mma_f: L1-GEMM2 with FUSED H construction.
// A[r, k] = relu(PQ[ia(r), k] + PQ[ib(r), 2048 + k] + b1[k]),  K = 2048.
// A-tile built in-kernel: LDG (L2-resident PQ) -> f32 add -> relu -> STS,
// software-pipelined: LDG issued before the MMA block, STS after it.
// ---------------------------------------------------------------------------
__global__ void __launch_bounds__(128, 2)
gemm_mma_f(const int* __restrict__ idxg,
           const __half* __restrict__ PQ,
           const __half* __restrict__ b1h,
           const __half* __restrict__ Bt,
           const float* __restrict__ bias,
           __half* __restrict__ C,
           int M, int N)
{
    const int K = 2048;
    extern __shared__ char smem[];
    const uint32_t sb = smem_u32(smem);
    const int tid = threadIdx.x;
    const int wid = tid >> 5;
    const int lane = tid & 31;
    const int wm = wid >> 1;
    const int wn = wid & 1;

    const size_t row0 = (size_t)blockIdx.y * 128;
    const size_t col0 = (size_t)blockIdx.x * 128;
    const __half* Bg = Bt + col0 * K;

    const int seg = tid & 3;
    const int rowc = tid >> 2;

    int eidx[4][2];
#pragma unroll
    for (int h = 0; h < 4; h++) {
        const size_t r = row0 + rowc + h * 32;
        eidx[h][0] = __ldg(idxg + 2 * r);
        eidx[h][1] = __ldg(idxg + 2 * r + 1);
    }

    const int nk = K / KC;   // 64

    // prologue: stages 0..2 (synchronous A build, async B)
#pragma unroll
    for (int c = 0; c < STG4 - 1; c++) {
        const uint32_t stoff = c * STAGE128;
        const int k0 = c * KC;
        const int ko = k0 + seg * 8;
        const uint4 bv = *(const uint4*)(b1h + ko);
#pragma unroll
        for (int h = 0; h < 4; h++) {
            const uint4 pv = __ldg((const uint4*)(PQ + (size_t)eidx[h][0] * 4096 + ko));
            const uint4 qv = __ldg((const uint4*)(PQ + (size_t)eidx[h][1] * 4096 + 2048 + ko));
            uint4 res;
            const __half2* ph = (const __half2*)&pv;
            const __half2* qh = (const __half2*)&qv;
            const __half2* bh = (const __half2*)&bv;
            __half2* rh = (__half2*)&res;
#pragma unroll
            for (int j = 0; j < 4; j++) {
                const float2 pf = __half22float2(ph[j]);
                const float2 qf = __half22float2(qh[j]);
                const float2 bf = __half22float2(bh[j]);
                float2 f;
                f.x = fmaxf(pf.x + qf.x + bf.x, 0.0f);
                f.y = fmaxf(pf.y + qf.y + bf.y, 0.0f);
                rh[j] = __float22half2_rn(f);
            }
            const int r = rowc + h * 32;
            *(uint4*)(smem + stoff + r * PITCH + seg * 16) = res;
            cp16(sb + stoff + TILE128 + r * PITCH + seg * 16,
                 Bg + (size_t)r * K + k0 + seg * 8);
        }
        cp_commit();
    }
    __syncthreads();   // make prologue STS visible before first ldmatrix

    float acc[4][8][4];
#pragma unroll
    for (int i = 0; i < 4; i++)
#pragma unroll
        for (int j = 0; j < 8; j++)
#pragma unroll
            for (int k = 0; k < 4; k++) acc[i][j][k] = 0.0f;

    const uint32_t aoff = (uint32_t)((wm * 64 + (lane & 15)) * PITCH + (lane >> 4) * 16);
    const uint32_t boff = (uint32_t)((wn * 64 + (lane & 7) + ((lane >> 4) << 3)) * PITCH
                                     + ((lane >> 3) & 1) * 16);

    for (int i = 0; i < nk; i++) {
        cp_wait<STG4 - 2>();
        __syncthreads();

        // issue A LDGs + B cp.async for stage i+3 (consumed after MMA block)
        const int c = i + STG4 - 1;
        uint4 pv[4], qv[4], bv;
        if (c < nk) {
            const int k0 = c * KC;
            const int ko = k0 + seg * 8;
            bv = *(const uint4*)(b1h + ko);
#pragma unroll
            for (int h = 0; h < 4; h++) {
                pv[h] = __ldg((const uint4*)(PQ + (size_t)eidx[h][0] * 4096 + ko));
                qv[h] = __ldg((const uint4*)(PQ + (size_t)eidx[h][1] * 4096 + 2048 + ko));
                cp16(sb + (c % STG4) * STAGE128 + TILE128 + (rowc + h * 32) * PITCH + seg * 16,
                     Bg + (size_t)(rowc + h * 32) * K + k0 + seg * 8);
            }
        }

        const uint32_t st = sb + (i % STG4) * STAGE128;
        const uint32_t aB = st + aoff;
        const uint32_t bB = st + TILE128 + boff;

#pragma unroll
        for (int ks = 0; ks < 2; ks++) {
            uint32_t af[4][4], bf[4][4];
#pragma unroll
            for (int mt = 0; mt < 4; mt++)
                ldm_x4(af[mt], aB + mt * (16 * PITCH) + ks * 32);
#pragma unroll
            for (int nt2 = 0; nt2 < 4; nt2++)
                ldm_x4(bf[nt2], bB + nt2 * (16 * PITCH) + ks * 32);
#pragma unroll
            for (int mt = 0; mt < 4; mt++)
#pragma unroll
                for (int nt2 = 0; nt2 < 4; nt2++) {
                    mma_f16(acc[mt][2 * nt2 + 0], af[mt], &bf[nt2][0]);
                    mma_f16(acc[mt][2 * nt2 + 1], af[mt], &bf[nt2][2]);
                }
        }

        // convert + STS the A fragments for stage c (LDGs have retired under MMAs)
        if (c < nk) {
            const uint32_t stoff = (c % STG4) * STAGE128;
            const __half2* bh = (const __half2*)&bv;
#pragma unroll
            for (int h = 0; h < 4; h++) {
                uint4 res;
                const __half2* ph = (const __half2*)&pv[h];
                const __half2* qh = (const __half2*)&qv[h];
                __half2* rh = (__half2*)&res;
#pragma unroll
                for (int j = 0; j < 4; j++) {
                    const float2 pf = __half22float2(ph[j]);
                    const float2 qf = __half22float2(qh[j]);
                    const float2 bf2 = __half22float2(bh[j]);
                    float2 f;
                    f.x = fmaxf(pf.x + qf.x + bf2.x, 0.0f);
                    f.y = fmaxf(pf.y + qf.y + bf2.y, 0.0f);
                    rh[j] = __float22half2_rn(f);
                }
                *(uint4*)(smem + stoff + (rowc + h * 32) * PITCH + seg * 16) = res;
            }
        }
        cp_commit();
    }

    const int lr = lane >> 2;
    const int lc = (lane & 3) * 2;
#pragma unroll
    for (int mt = 0; mt < 4; mt++) {
#pragma unroll
        for (int nt = 0; nt < 8; nt++) {
            const size_t r0 = row0 + wm * 64 + mt * 16 + lr;
            const size_t cc = col0 + wn * 64 + nt * 8 + lc;
            const float bx = __ldg(bias + cc);
            const float by = __ldg(bias + cc + 1);
#pragma unroll
            for (int hh = 0; hh < 2; hh++) {
                const size_t r = r0 + hh * 8;
                __half hp[2];
                hp[0] = __float2half_rn(fmaxf(acc[mt][nt][hh * 2 + 0] + bx, 0.0f));
                hp[1] = __float2half_rn(fmaxf(acc[mt][nt][hh * 2 + 1] + by, 0.0f));
                *(uint32_t*)(C + r * N + cc) = *(uint32_t*)hp;
            }
        }
    }
}

// ---------------------------------------------------------------------------
// gemm_mma_sk: split-K kernel -> raw f32 partials.
// ---------------------------------------------------------------------------
__global__ void __launch_bounds__(128, 2)
gemm_mma_sk(const __half* __restrict__ A,
            const __half* __restrict__ Bt,
            float* __restrict__ P,
            int M, int N, int K, int klen)
{
    extern __shared__ char smem[];
    const uint32_t sb = smem_u32(smem);
    const int tid = threadIdx.x;
    const int wid = tid >> 5;
    const int lane = tid & 31;
    const int wm = wid >> 1;
    const int wn = wid & 1;

    const size_t row0 = (size_t)blockIdx.y * 128;
    const size_t col0 = (size_t)blockIdx.x * 128;
    const int kbase = blockIdx.z * klen;
    const __half* Ag = A + row0 * K + kbase;
    const __half* Bg = Bt + col0 * K + kbase;
    float* Pg = P + (size_t)blockIdx.z * M * N;

    const int seg = tid & 3;
    const int rowc = tid >> 2;

    const int nk = klen / KC;

#pragma unroll
    for (int c = 0; c < STG4 - 1; c++) {
        if (c < nk) {
            const uint32_t st = sb + c * STAGE128;
            const int k0 = c * KC;
#pragma unroll
            for (int h = 0; h < 4; h++) {
                const int r = rowc + h * 32;
                const size_t go = (size_t)r * K + k0 + seg * 8;
                const uint32_t so = r * PITCH + seg * 16;
                cp16(st + so, Ag + go);
                cp16(st + TILE128 + so, Bg + go);
            }
        }
        cp_commit();
    }

    float acc[4][8][4];
#pragma unroll
    for (int i = 0; i < 4; i++)
#pragma unroll
        for (int j = 0; j < 8; j++)
#pragma unroll
            for (int k = 0; k < 4; k++) acc[i][j][k] = 0.0f;

    const uint32_t aoff = (uint32_t)((wm * 64 + (lane & 15)) * PITCH + (lane >> 4) * 16);
    const uint32_t boff = (uint32_t)((wn * 64 + (lane & 7) + ((lane >> 4) << 3)) * PITCH
                                     + ((lane >> 3) & 1) * 16);

    for (int i = 0; i < nk; i++) {
        cp_wait<STG4 - 2>();
        __syncthreads();

        const uint32_t st = sb + (i % STG4) * STAGE128;
        const uint32_t aB = st + aoff;
        const uint32_t bB = st + TILE128 + boff;

        uint32_t af[2][4][4], bf[2][4][4];
#pragma unroll
        for (int ks = 0; ks < 2; ks++) {
#pragma unroll
            for (int mt = 0; mt < 4; mt++)
                ldm_x4(af[ks][mt], aB + mt * (16 * PITCH) + ks * 32);
#pragma unroll
            for (int nt2 = 0; nt2 < 4; nt2++)
                ldm_x4(bf[ks][nt2], bB + nt2 * (16 * PITCH) + ks * 32);
        }
#pragma unroll
        for (int ks = 0; ks < 2; ks++)
#pragma unroll
            for (int mt = 0; mt < 4; mt++)
#pragma unroll
                for (int nt2 = 0; nt2 < 4; nt2++) {
                    mma_f16(acc[mt][2 * nt2 + 0], af[ks][mt], &bf[ks][nt2][0]);
                    mma_f16(acc[mt][2 * nt2 + 1], af[ks][mt], &bf[ks][nt2][2]);
                }

        const int c = i + STG4 - 1;
        if (c < nk) {
            const uint32_t stw = sb + (c % STG4) * STAGE128;
            const int k0 = c * KC;
#pragma unroll
            for (int h = 0; h < 4; h++) {
                const int r = rowc + h * 32;
                const size_t go = (size_t)r * K + k0 + seg * 8;
                const uint32_t so = r * PITCH + seg * 16;
                cp16(stw + so, Ag + go);
                cp16(stw + TILE128 + so, Bg + go);
            }
        }
        cp_commit();
    }

    const int lr = lane >> 2;
    const int lc = (lane & 3) * 2;
#pragma unroll
    for (int mt = 0; mt < 4; mt++) {
#pragma unroll
        for (int nt = 0; nt < 8; nt++) {
            const size_t r0 = row0 + wm * 64 + mt * 16 + lr;
            const size_t cc = col0 + wn * 64 + nt * 8 + lc;
#pragma unroll
            for (int hh = 0; hh < 2; hh++) {
                const size_t r = r0 + hh * 8;
                float2 v;
                v.x = acc[mt][nt][hh * 2 + 0];
                v.y = acc[mt][nt][hh * 2 + 1];
                *(float2*)(Pg + r * N + cc) = v;
            }
        }
    }
}

template <int ACT>
__global__ void reduce_sk(const float* __restrict__ P,
                          const float* __restrict__ bias,
                          __half* __restrict__ C,
                          int MN, int N, int S)
{
    const int idx = (blockIdx.x * blockDim.x + threadIdx.x) * 4;
    if (idx >= MN) return;
    float4 a = *(const float4*)(P + idx);
    for (int s = 1; s < S; s++) {
        const float4 b = *(const float4*)(P + (size_t)s * MN + idx);
        a.x += b.x; a.y += b.y; a.z += b.z; a.w += b.w;
    }
    const int col = idx % N;
    const float4 bv = *(const float4*)(bias + col);
    __half h[4];
    h[0] = __float2half_rn(apply_act<ACT>(a.x + bv.x));
    h[1] = __float2half_rn(apply_act<ACT>(a.y + bv.y));
    h[2] = __float2half_rn(apply_act<ACT>(a.z + bv.z));
    h[3] = __float2half_rn(apply_act<ACT>(a.w + bv.w));
    *(uint2*)(C + idx) = *(uint2*)h;
}

// ---------------------------------------------------------------------------
// launch
// ---------------------------------------------------------------------------
static float* g_skP_ptr = nullptr;

static void launch_gemm(int act, const __half* A, const __half* Bt,
                        const float* bias, __half* C, int M, int N, int K)
{
    const int ctas = (M / 128) * (N / 128);
    const int iters = K / KC;

    int S = 1;
    if (ctas < 296 && iters >= 4) {
        while (S < 8 && ctas * (S * 2) <= 592 &&
               (iters % (S * 2)) == 0 && (iters / (S * 2)) >= 2)
            S *= 2;
    }

    if (S > 1) {
        dim3 g(N / 128, M / 128, S);
        gemm_mma_sk<<<g, 128, GSMEM128>>>(A, Bt, g_skP_ptr, M, N, K, K / S);
        const int MN = M * N;
        const int thr = 256;
        const int blocks = (MN / 4 + thr - 1) / thr;
        if (act == ACT_RELU)
            reduce_sk<ACT_RELU><<<blocks, thr>>>(g_skP_ptr, bias, C, MN, N, S);
        else
            reduce_sk<ACT_TANH><<<blocks, thr>>>(g_skP_ptr, bias, C, MN, N, S);
    } else {
        dim3 g(N / 128, M / 128);
        if (act == ACT_RELU)
            gemm_mma<ACT_RELU><<<g, 128, GSMEM128>>>(A, Bt, bias, C, M, N, K);
        else
            gemm_mma<ACT_TANH><<<g, 128, GSMEM128>>>(A, Bt, bias, C, M, N, K);
    }
}

extern "C" void kernel_launch(void* const* d_in, const int* in_sizes, int n_in,
                              void* d_out, int out_size)
{
    const int*   leaf = (const int*)  d_in[0];
    const float* ent  = (const float*)d_in[1];
    const float* th   = (const float*)d_in[2];
    const float* w1   = (const float*)d_in[3];
    const float* b1   = (const float*)d_in[4];
    const float* w2   = (const float*)d_in[5];
    const float* b2   = (const float*)d_in[6];
    const float* o1   = (const float*)d_in[7];
    const float* ob1  = (const float*)d_in[8];
    const float* o2   = (const float*)d_in[9];
    const float* ob2  = (const float*)d_in[10];
    const float* h1   = (const float*)d_in[11];
    const float* hb1  = (const float*)d_in[12];
    const float* h2   = (const float*)d_in[13];
    const float* hb2  = (const float*)d_in[14];
    const float* h3   = (const float*)d_in[15];
    const float* hb3  = (const float*)d_in[16];
    const float* h4   = (const float*)d_in[17];
    const float* hb4  = (const float*)d_in[18];

    __half *bufA, *bufB, *H, *z1, *z2, *z3, *wT, *wPQT, *emb16, *PQ, *b1h;
    float *zeroB, *hb1p;
    cudaGetSymbolAddress((void**)&bufA, g_bufA);
    cudaGetSymbolAddress((void**)&bufB, g_bufB);
    cudaGetSymbolAddress((void**)&H,    g_bufH);
    cudaGetSymbolAddress((void**)&z1,   g_z1);
    cudaGetSymbolAddress((void**)&z2,   g_z2);
    cudaGetSymbolAddress((void**)&z3,   g_z3);
    cudaGetSymbolAddress((void**)&wT,   g_wT);
    cudaGetSymbolAddress((void**)&wPQT, g_wPQT);
    cudaGetSymbolAddress((void**)&emb16, g_emb16);
    cudaGetSymbolAddress((void**)&PQ,   g_PQ);
    cudaGetSymbolAddress((void**)&b1h,  g_b1h);
    cudaGetSymbolAddress((void**)&zeroB, g_zeroBias);
    cudaGetSymbolAddress((void**)&hb1p, g_hb1p);
    cudaGetSymbolAddress((void**)&g_skP_ptr, g_skP);

    cudaFuncSetAttribute(gemm_mma<ACT_RELU>,
                         cudaFuncAttributeMaxDynamicSharedMemorySize, GSMEM128);
    cudaFuncSetAttribute(gemm_mma<ACT_TANH>,
                         cudaFuncAttributeMaxDynamicSharedMemorySize, GSMEM128);
    cudaFuncSetAttribute(gemm_mma<ACT_NONE>,
                         cudaFuncAttributeMaxDynamicSharedMemorySize, GSMEM128);
    cudaFuncSetAttribute(gemm_mma_sk,
                         cudaFuncAttributeMaxDynamicSharedMemorySize, GSMEM128);
    cudaFuncSetAttribute(gemm_mma_f,
                         cudaFuncAttributeMaxDynamicSharedMemorySize, GSMEM128);

    // 0) prep
    emb_cvt_kernel<<<NENT_, E_ / 4>>>(ent, emb16);
    b1_cvt_kernel<<<8, 256>>>(b1, b1h);
    headbias_kernel<<<4, 128>>>(th, h1, hb1, hb1p);
    {
        TransJobs jobs;
        const float* Ws[9]  = {w1, w1 + (size_t)512 * 2048, w1, w2, o1, o2,
                               h1 + (size_t)512 * 512, h2, h3};
        __half* Wts[9] = {wPQT, wPQT + (size_t)2048 * 512,
                          wT + W1T_OFF, wT + W2T_OFF, wT + O1T_OFF, wT + O2T_OFF,
                          wT + H1T_OFF, wT + H2T_OFF, wT + H3T_OFF};
        const int Ks[9] = {512, 512, 2 * E_, 4 * E_, E_, 4 * E_, 2 * E_, E_, E_ / 2};
        const int Ns[9] = {4 * E_, 4 * E_, 4 * E_, E_, 4 * E_, E_, E_, E_ / 2, E_ / 4};
        int acc = 0;
        for (int j = 0; j < 9; j++) {
            jobs.W[j] = Ws[j]; jobs.Wt[j] = Wts[j];
            jobs.K[j] = Ks[j]; jobs.N[j] = Ns[j];
            jobs.ofs[j] = acc;
            acc += (Ns[j] / 32) * (Ks[j] / 32);
        }
        jobs.ofs[9] = acc;
        transpose_all<<<acc, dim3(32, 8)>>>(jobs);
    }

    // 1) PQ = emb16 @ [w1_top | w1_bot]  : [2048, 4096]
    {
        dim3 g(4096 / 128, NENTP / 128);
        gemm_mma<ACT_NONE><<<g, 128, GSMEM128>>>(emb16, wPQT, zeroB, PQ,
                                                 NENTP, 4096, 512);
    }

    // 2) level 1: fused H-construction GEMM2 -> bufB [32768, 512]
    {
        const int rows = B_ * NT_ * (NL_ / 2);    // 32768
        dim3 g(E_ / 128, rows / 128);
        gemm_mma_f<<<g, 128, GSMEM128>>>(leaf, PQ, b1h, wT + W2T_OFF, b2,
                                         bufB, rows, E_);
    }

    // 3) tree reduction levels 2..6
    __half* in  = bufB;
    __half* out = bufA;
    int n = NL_ / 2;
    while (n > 1) {
        const int rows = B_ * NT_ * (n / 2);
        launch_gemm(ACT_RELU, in, wT + W1T_OFF, b1, H, rows, 4 * E_, 2 * E_);
        launch_gemm(ACT_RELU, H, wT + W2T_OFF, b2, out, rows, E_, 4 * E_);
        __half* tp = in; in = out; out = tp;
        n >>= 1;
    }
    // after 5 swaps starting from in=bufB: in=bufA (root)

    // 4) one2one
    {
        const int rows = B_ * NT_;
        launch_gemm(ACT_RELU, in, wT + O1T_OFF, ob1, H, rows, 4 * E_, E_);
        launch_gemm(ACT_TANH, H, wT + O2T_OFF, ob2, out, rows, E_, 4 * E_);
    }
    // root2 in `out` = bufB : [512, 1024]

    // 5) head (th folded into hb1p; K = 1024)
    launch_gemm(ACT_RELU, out, wT + H1T_OFF, hb1p, z1, B_, E_, NT_ * E_);
    launch_gemm(ACT_RELU, z1, wT + H2T_OFF, hb2, z2, B_, E_ / 2, E_);
    launch_gemm(ACT_RELU, z2, wT + H3T_OFF, hb3, z3, B_, E_ / 4, E_ / 2);

    // 6) final dot + sigmoid
    final_kernel<<<(B_ * 32 + 255) / 256, 256>>>(z3, h4, hb4, (float*)d_out);
}

// round 16
// speedup vs baseline: 1.0494x; 1.0494x over previous
#include <cuda_runtime.h>
#include <cuda_fp16.h>
#include <math.h>
#include <stdint.h>

// ===========================================================================
// LogicRecursiveNN on GB300 (plain sm_103 target -> mma.sync path).
// Single-pass fp16 GEMMs, f32 accumulate.  (R14 structure, faster prep.)
// ALGEBRAIC OPTS:
//  - L1-G1 factored through the 2000-entry dictionary: PQ = emb @ [w1t|w1b];
//    H = relu(P[ia] + Q[ib] + b1) via a gather-add-relu kernel.
//  - Head: th batch-constant -> th @ h1_top folded into bias.
// Hot GEMMs: 128x128 CTA, 128 thr, warp tile 64x64, KC=32, 4 stg, 2 CTAs/SM.
// Tail GEMMs (< 1 wave): split-K (S<=8) + reduce.
// ===========================================================================

#define B_    512
#define NT_   2
#define NL_   64
#define E_    512
#define T_    512

#define SB_   ((size_t)B_ * NT_ * NL_ * E_ / 2)
#define SH_   ((size_t)B_ * NT_ * (NL_/2) * 4 * E_)
#define SZ1_  ((size_t)B_ * E_)
#define SZ2_  ((size_t)B_ * (E_/2))
#define SZ3_  ((size_t)B_ * (E_/4))
#define NENT_ 2000
#define NENTP 2048

__device__ __half g_bufA[SB_];
__device__ __half g_bufB[SB_];
__device__ __half g_bufH[SH_];
__device__ __half g_z1[SZ1_];
__device__ __half g_z2[SZ2_];
__device__ __half g_z3[SZ3_];
__device__ __half g_wT[6193152];
__device__ __half g_wPQT[(size_t)4096 * 512];
__device__ __half g_emb16[(size_t)NENTP * E_];
__device__ __half g_PQ[(size_t)NENTP * 4096];
__device__ float  g_skP[8388608];
__device__ float  g_zeroBias[4096];
__device__ float  g_hb1p[E_];

#define W1T_OFF  0          // [2048,1024]
#define W2T_OFF  2097152    // [512,2048]
#define O1T_OFF  3145728    // [2048,512]
#define O2T_OFF  4194304    // [512,2048]
#define H1T_OFF  5242880    // [512,1024]  (h1 bottom only)
#define H2T_OFF  6029312    // [256,512]
#define H3T_OFF  6160384    // [128,256]

// ---------------------------------------------------------------------------
// helpers
// ---------------------------------------------------------------------------
__device__ __forceinline__ uint32_t smem_u32(const void* p) {
    uint32_t a;
    asm("{ .reg .u64 t; cvta.to.shared.u64 t, %1; cvt.u32.u64 %0, t; }"
        : "=r"(a) : "l"(p));
    return a;
}
__device__ __forceinline__ void cp16(uint32_t dst, const void* src) {
    asm volatile("cp.async.cg.shared.global [%0], [%1], 16;"
                 :: "r"(dst), "l"(src) : "memory");
}
__device__ __forceinline__ void cp_commit() {
    asm volatile("cp.async.commit_group;" ::: "memory");
}
template <int N>
__device__ __forceinline__ void cp_wait() {
    asm volatile("cp.async.wait_group %0;" :: "n"(N) : "memory");
}
__device__ __forceinline__ void ldm_x4(uint32_t* r, uint32_t addr) {
    asm volatile("ldmatrix.sync.aligned.m8n8.x4.shared.b16 {%0,%1,%2,%3}, [%4];"
                 : "=r"(r[0]), "=r"(r[1]), "=r"(r[2]), "=r"(r[3]) : "r"(addr));
}
__device__ __forceinline__ void mma_f16(float* c, const uint32_t* a, const uint32_t* b) {
    asm volatile(
        "mma.sync.aligned.m16n8k16.row.col.f32.f16.f16.f32 "
        "{%0,%1,%2,%3}, {%4,%5,%6,%7}, {%8,%9}, {%0,%1,%2,%3};"
        : "+f"(c[0]), "+f"(c[1]), "+f"(c[2]), "+f"(c[3])
        : "r"(a[0]), "r"(a[1]), "r"(a[2]), "r"(a[3]), "r"(b[0]), "r"(b[1]));
}

#define ACT_RELU 0
#define ACT_TANH 1
#define ACT_NONE 2
template <int ACT>
__device__ __forceinline__ float apply_act(float x) {
    if (ACT == ACT_RELU) return fmaxf(x, 0.0f);
    if (ACT == ACT_TANH) return tanhf(x);
    return x;
}

// ---------------------------------------------------------------------------
// small kernels
// ---------------------------------------------------------------------------
__global__ void emb_cvt_kernel(const float* __restrict__ emb,
                               __half* __restrict__ out)
{
    const size_t o = (size_t)blockIdx.x * E_ + threadIdx.x * 4;
    const float4 v = *(const float4*)(emb + o);
    __half h[4];
    h[0] = __float2half_rn(v.x); h[1] = __float2half_rn(v.y);
    h[2] = __float2half_rn(v.z); h[3] = __float2half_rn(v.w);
    *(uint2*)(out + o) = *(uint2*)h;
}

struct TransJobs {
    const float* W[9];
    __half* Wt[9];
    int K[9], N[9];
    int ofs[10];
};

// 64x64 tiles, block (32,8); all K,N are multiples of 64.
__global__ void transpose_all(TransJobs jobs)
{
    __shared__ float t[64][65];
    int j = 0;
#pragma unroll
    for (int q = 1; q < 9; q++) if ((int)blockIdx.x >= jobs.ofs[q]) j = q;
    const int tile = blockIdx.x - jobs.ofs[j];
    const int K = jobs.K[j], N = jobs.N[j];
    const int tilesX = N / 64;
    const int bx = (tile % tilesX) * 64;
    const int by = (tile / tilesX) * 64;
    const float* W = jobs.W[j];
    __half* Wt = jobs.Wt[j];
    const int tx = threadIdx.x;

    for (int i = threadIdx.y; i < 64; i += 8) {
        t[i][tx]      = W[(size_t)(by + i) * N + bx + tx];
        t[i][tx + 32] = W[(size_t)(by + i) * N + bx + tx + 32];
    }
    __syncthreads();
    for (int i = threadIdx.y; i < 64; i += 8) {
        Wt[(size_t)(bx + i) * K + by + tx]      = __float2half_rn(t[tx][i]);
        Wt[(size_t)(bx + i) * K + by + tx + 32] = __float2half_rn(t[tx + 32][i]);
    }
}

// H[row] = relu(PQ[ia, 0:2048] + PQ[ib, 2048:4096] + b1)
__global__ void gaddrelu_kernel(const int* __restrict__ idx,
                                const __half* __restrict__ PQ,
                                const float* __restrict__ b1,
                                __half* __restrict__ H)
{
    const int row = blockIdx.x;
    const int ia = __ldg(idx + 2 * row);
    const int ib = __ldg(idx + 2 * row + 1);
    const int off = threadIdx.x * 8;
    const uint4 pv = *(const uint4*)(PQ + (size_t)ia * 4096 + off);
    const uint4 qv = *(const uint4*)(PQ + (size_t)ib * 4096 + 2048 + off);
    const __half2* ph = (const __half2*)&pv;
    const __half2* qh = (const __half2*)&qv;
    const float4 b0 = *(const float4*)(b1 + off);
    const float4 b4 = *(const float4*)(b1 + off + 4);
    const float bb[8] = {b0.x, b0.y, b0.z, b0.w, b4.x, b4.y, b4.z, b4.w};
    __half hres[8];
#pragma unroll
    for (int i = 0; i < 4; i++) {
        const float2 pf = __half22float2(ph[i]);
        const float2 qf = __half22float2(qh[i]);
        hres[2 * i]     = __float2half_rn(fmaxf(pf.x + qf.x + bb[2 * i], 0.0f));
        hres[2 * i + 1] = __float2half_rn(fmaxf(pf.y + qf.y + bb[2 * i + 1], 0.0f));
    }
    *(uint4*)(H + (size_t)row * 2048 + off) = *(uint4*)hres;
}

// hb1'[n] = hb1[n] + sum_t th[t] * h1[t, n]
__global__ void headbias_kernel(const float* __restrict__ th,
                                const float* __restrict__ h1,
                                const float* __restrict__ hb1,
                                float* __restrict__ outb)
{
    const int n = blockIdx.x * blockDim.x + threadIdx.x;
    float s = hb1[n];
    for (int t = 0; t < T_; t++)
        s = fmaf(th[t], h1[(size_t)t * E_ + n], s);
    outb[n] = s;
}

__global__ void final_kernel(const __half* __restrict__ z3,
                             const float* __restrict__ w,
                             const float* __restrict__ b0,
                             float* __restrict__ out)
{
    const int warp = (blockIdx.x * blockDim.x + threadIdx.x) >> 5;
    const int lane = threadIdx.x & 31;
    if (warp >= B_) return;
    const size_t base = (size_t)warp * 128;
    float s = 0.0f;
#pragma unroll
    for (int i = lane; i < 128; i += 32)
        s = fmaf(__half2float(z3[base + i]), w[i], s);
#pragma unroll
    for (int o = 16; o > 0; o >>= 1) s += __shfl_down_sync(0xFFFFFFFFu, s, o);
    if (lane == 0) {
        const float x = s + b0[0];
        out[warp] = 1.0f / (1.0f + expf(-x));
    }
}

// ---------------------------------------------------------------------------
// GEMM tiling constants
// ---------------------------------------------------------------------------
#define KC       32
#define PITCH    80
#define STG4     4
#define TILE128  (128 * PITCH)
#define STAGE128 (2 * TILE128)
#define GSMEM128 (STG4 * STAGE128)           // 81920 (x2 CTAs = 160 KB/SM)

// ---------------------------------------------------------------------------
// gemm_mma: full-K kernel, bias+act epilogue, fp16 out.
// ---------------------------------------------------------------------------
template <int ACT>
__global__ void __launch_bounds__(128, 2)
gemm_mma(const __half* __restrict__ A,
         const __half* __restrict__ Bt,
         const float* __restrict__ bias,
         __half* __restrict__ C,
         int M, int N, int K)
{
    extern __shared__ char smem[];
    const uint32_t sb = smem_u32(smem);
    const int tid = threadIdx.x;
    const int wid = tid >> 5;
    const int lane = tid & 31;
    const int wm = wid >> 1;
    const int wn = wid & 1;

    const size_t row0 = (size_t)blockIdx.y * 128;
    const size_t col0 = (size_t)blockIdx.x * 128;
    const __half* Ag = A + row0 * K;
    const __half* Bg = Bt + col0 * K;

    const int seg = tid & 3;
    const int rowc = tid >> 2;

    const int nk = K / KC;

#pragma unroll
    for (int c = 0; c < STG4 - 1; c++) {
        if (c < nk) {
            const uint32_t st = sb + c * STAGE128;
            const int k0 = c * KC;
#pragma unroll
            for (int h = 0; h < 4; h++) {
                const int r = rowc + h * 32;
                const size_t go = (size_t)r * K + k0 + seg * 8;
                const uint32_t so = r * PITCH + seg * 16;
                cp16(st + so, Ag + go);
                cp16(st + TILE128 + so, Bg + go);
            }
        }
        cp_commit();
    }

    float acc[4][8][4];
#pragma unroll
    for (int i = 0; i < 4; i++)
#pragma unroll
        for (int j = 0; j < 8; j++)
#pragma unroll
            for (int k = 0; k < 4; k++) acc[i][j][k] = 0.0f;

    const uint32_t aoff = (uint32_t)((wm * 64 + (lane & 15)) * PITCH + (lane >> 4) * 16);
    const uint32_t boff = (uint32_t)((wn * 64 + (lane & 7) + ((lane >> 4) << 3)) * PITCH
                                     + ((lane >> 3) & 1) * 16);

    for (int i = 0; i < nk; i++) {
        cp_wait<STG4 - 2>();
        __syncthreads();

        const uint32_t st = sb + (i % STG4) * STAGE128;
        const uint32_t aB = st + aoff;
        const uint32_t bB = st + TILE128 + boff;

        uint32_t af[2][4][4], bf[2][4][4];
#pragma unroll
        for (int ks = 0; ks < 2; ks++) {
#pragma unroll
            for (int mt = 0; mt < 4; mt++)
                ldm_x4(af[ks][mt], aB + mt * (16 * PITCH) + ks * 32);
#pragma unroll
            for (int nt2 = 0; nt2 < 4; nt2++)
                ldm_x4(bf[ks][nt2], bB + nt2 * (16 * PITCH) + ks * 32);
        }
#pragma unroll
        for (int ks = 0; ks < 2; ks++)
#pragma unroll
            for (int mt = 0; mt < 4; mt++)
#pragma unroll
                for (int nt2 = 0; nt2 < 4; nt2++) {
                    mma_f16(acc[mt][2 * nt2 + 0], af[ks][mt], &bf[ks][nt2][0]);
                    mma_f16(acc[mt][2 * nt2 + 1], af[ks][mt], &bf[ks][nt2][2]);
                }

        const int c = i + STG4 - 1;
        if (c < nk) {
            const uint32_t stw = sb + (c % STG4) * STAGE128;
            const int k0 = c * KC;
#pragma unroll
            for (int h = 0; h < 4; h++) {
                const int r = rowc + h * 32;
                const size_t go = (size_t)r * K + k0 + seg * 8;
                const uint32_t so = r * PITCH + seg * 16;
                cp16(stw + so, Ag + go);
                cp16(stw + TILE128 + so, Bg + go);
            }
        }
        cp_commit();
    }

    const int lr = lane >> 2;
    const int lc = (lane & 3) * 2;
#pragma unroll
    for (int mt = 0; mt < 4; mt++) {
#pragma unroll
        for (int nt = 0; nt < 8; nt++) {
            const size_t r0 = row0 + wm * 64 + mt * 16 + lr;
            const size_t cc = col0 + wn * 64 + nt * 8 + lc;
            const float bx = __ldg(bias + cc);
            const float by = __ldg(bias + cc + 1);
#pragma unroll
            for (int hh = 0; hh < 2; hh++) {
                const size_t r = r0 + hh * 8;
                __half hp[2];
                hp[0] = __float2half_rn(apply_act<ACT>(acc[mt][nt][hh * 2 + 0] + bx));
                hp[1] = __float2half_rn(apply_act<ACT>(acc[mt][nt][hh * 2 + 1] + by));
                *(uint32_t*)(C + r * N + cc) = *(uint32_t*)hp;
            }
        }
    }
}

// ---------------------------------------------------------------------------
// gemm_mma_sk: split-K kernel -> raw f32 partials.
// ---------------------------------------------------------------------------
__global__ void __launch_bounds__(128, 2)
gemm_mma_sk(const __half* __restrict__ A,
            const __half* __restrict__ Bt,
            float* __restrict__ P,
            int M, int N, int K, int klen)
{
    extern __shared__ char smem[];
    const uint32_t sb = smem_u32(smem);
    const int tid = threadIdx.x;
    const int wid = tid >> 5;
    const int lane = tid & 31;
    const int wm = wid >> 1;
    const int wn = wid & 1;

    const size_t row0 = (size_t)blockIdx.y * 128;
    const size_t col0 = (size_t)blockIdx.x * 128;
    const int kbase = blockIdx.z * klen;
    const __half* Ag = A + row0 * K + kbase;
    const __half* Bg = Bt + col0 * K + kbase;
    float* Pg = P + (size_t)blockIdx.z * M * N;

    const int seg = tid & 3;
    const int rowc = tid >> 2;

    const int nk = klen / KC;

#pragma unroll
    for (int c = 0; c < STG4 - 1; c++) {
        if (c < nk) {
            const uint32_t st = sb + c * STAGE128;
            const int k0 = c * KC;
#pragma unroll
            for (int h = 0; h < 4; h++) {
                const int r = rowc + h * 32;
                const size_t go = (size_t)r * K + k0 + seg * 8;
                const uint32_t so = r * PITCH + seg * 16;
                cp16(st + so, Ag + go);
                cp16(st + TILE128 + so, Bg + go);
            }
        }
        cp_commit();
    }

    float acc[4][8][4];
#pragma unroll
    for (int i = 0; i < 4; i++)
#pragma unroll
        for (int j = 0; j < 8; j++)
#pragma unroll
            for (int k = 0; k < 4; k++) acc[i][j][k] = 0.0f;

    const uint32_t aoff = (uint32_t)((wm * 64 + (lane & 15)) * PITCH + (lane >> 4) * 16);
    const uint32_t boff = (uint32_t)((wn * 64 + (lane & 7) + ((lane >> 4) << 3)) * PITCH
                                     + ((lane >> 3) & 1) * 16);

    for (int i = 0; i < nk; i++) {
        cp_wait<STG4 - 2>();
        __syncthreads();

        const uint32_t st = sb + (i % STG4) * STAGE128;
        const uint32_t aB = st + aoff;
        const uint32_t bB = st + TILE128 + boff;

        uint32_t af[2][4][4], bf[2][4][4];
#pragma unroll
        for (int ks = 0; ks < 2; ks++) {
#pragma unroll
            for (int mt = 0; mt < 4; mt++)
                ldm_x4(af[ks][mt], aB + mt * (16 * PITCH) + ks * 32);
#pragma unroll
            for (int nt2 = 0; nt2 < 4; nt2++)
                ldm_x4(bf[ks][nt2], bB + nt2 * (16 * PITCH) + ks * 32);
        }
#pragma unroll
        for (int ks = 0; ks < 2; ks++)
#pragma unroll
            for (int mt = 0; mt < 4; mt++)
#pragma unroll
                for (int nt2 = 0; nt2 < 4; nt2++) {
                    mma_f16(acc[mt][2 * nt2 + 0], af[ks][mt], &bf[ks][nt2][0]);
                    mma_f16(acc[mt][2 * nt2 + 1], af[ks][mt], &bf[ks][nt2][2]);
                }

        const int c = i + STG4 - 1;
        if (c < nk) {
            const uint32_t stw = sb + (c % STG4) * STAGE128;
            const int k0 = c * KC;
#pragma unroll
            for (int h = 0; h < 4; h++) {
                const int r = rowc + h * 32;
                const size_t go = (size_t)r * K + k0 + seg * 8;
                const uint32_t so = r * PITCH + seg * 16;
                cp16(stw + so, Ag + go);
                cp16(stw + TILE128 + so, Bg + go);
            }
        }
        cp_commit();
    }

    const int lr = lane >> 2;
    const int lc = (lane & 3) * 2;
#pragma unroll
    for (int mt = 0; mt < 4; mt++) {
#pragma unroll
        for (int nt = 0; nt < 8; nt++) {
            const size_t r0 = row0 + wm * 64 + mt * 16 + lr;
            const size_t cc = col0 + wn * 64 + nt * 8 + lc;
#pragma unroll
            for (int hh = 0; hh < 2; hh++) {
                const size_t r = r0 + hh * 8;
                float2 v;
                v.x = acc[mt][nt][hh * 2 + 0];
                v.y = acc[mt][nt][hh * 2 + 1];
                *(float2*)(Pg + r * N + cc) = v;
            }
        }
    }
}

template <int ACT>
__global__ void reduce_sk(const float* __restrict__ P,
                          const float* __restrict__ bias,
                          __half* __restrict__ C,
                          int MN, int N, int S)
{
    const int idx = (blockIdx.x * blockDim.x + threadIdx.x) * 4;
    if (idx >= MN) return;
    float4 a = *(const float4*)(P + idx);
    for (int s = 1; s < S; s++) {
        const float4 b = *(const float4*)(P + (size_t)s * MN + idx);
        a.x += b.x; a.y += b.y; a.z += b.z; a.w += b.w;
    }
    const int col = idx % N;
    const float4 bv = *(const float4*)(bias + col);
    __half h[4];
    h[0] = __float2half_rn(apply_act<ACT>(a.x + bv.x));
    h[1] = __float2half_rn(apply_act<ACT>(a.y + bv.y));
    h[2] = __float2half_rn(apply_act<ACT>(a.z + bv.z));
    h[3] = __float2half_rn(apply_act<ACT>(a.w + bv.w));
    *(uint2*)(C + idx) = *(uint2*)h;
}

// ---------------------------------------------------------------------------
// launch
// ---------------------------------------------------------------------------
static float* g_skP_ptr = nullptr;

static void launch_gemm(int act, const __half* A, const __half* Bt,
                        const float* bias, __half* C, int M, int N, int K)
{
    const int ctas = (M / 128) * (N / 128);
    const int iters = K / KC;

    int S = 1;
    if (ctas < 296 && iters >= 4) {
        while (S < 8 && ctas * (S * 2) <= 592 &&
               (iters % (S * 2)) == 0 && (iters / (S * 2)) >= 2)
            S *= 2;
    }

    if (S > 1) {
        dim3 g(N / 128, M / 128, S);
        gemm_mma_sk<<<g, 128, GSMEM128>>>(A, Bt, g_skP_ptr, M, N, K, K / S);
        const int MN = M * N;
        const int thr = 256;
        const int blocks = (MN / 4 + thr - 1) / thr;
        if (act == ACT_RELU)
            reduce_sk<ACT_RELU><<<blocks, thr>>>(g_skP_ptr, bias, C, MN, N, S);
        else
            reduce_sk<ACT_TANH><<<blocks, thr>>>(g_skP_ptr, bias, C, MN, N, S);
    } else {
        dim3 g(N / 128, M / 128);
        if (act == ACT_RELU)
            gemm_mma<ACT_RELU><<<g, 128, GSMEM128>>>(A, Bt, bias, C, M, N, K);
        else
            gemm_mma<ACT_TANH><<<g, 128, GSMEM128>>>(A, Bt, bias, C, M, N, K);
    }
}

extern "C" void kernel_launch(void* const* d_in, const int* in_sizes, int n_in,
                              void* d_out, int out_size)
{
    const int*   leaf = (const int*)  d_in[0];
    const float* ent  = (const float*)d_in[1];
    const float* th   = (const float*)d_in[2];
    const float* w1   = (const float*)d_in[3];
    const float* b1   = (const float*)d_in[4];
    const float* w2   = (const float*)d_in[5];
    const float* b2   = (const float*)d_in[6];
    const float* o1   = (const float*)d_in[7];
    const float* ob1  = (const float*)d_in[8];
    const float* o2   = (const float*)d_in[9];
    const float* ob2  = (const float*)d_in[10];
    const float* h1   = (const float*)d_in[11];
    const float* hb1  = (const float*)d_in[12];
    const float* h2   = (const float*)d_in[13];
    const float* hb2  = (const float*)d_in[14];
    const float* h3   = (const float*)d_in[15];
    const float* hb3  = (const float*)d_in[16];
    const float* h4   = (const float*)d_in[17];
    const float* hb4  = (const float*)d_in[18];

    __half *bufA, *bufB, *H, *z1, *z2, *z3, *wT, *wPQT, *emb16, *PQ;
    float *zeroB, *hb1p;
    cudaGetSymbolAddress((void**)&bufA, g_bufA);
    cudaGetSymbolAddress((void**)&bufB, g_bufB);
    cudaGetSymbolAddress((void**)&H,    g_bufH);
    cudaGetSymbolAddress((void**)&z1,   g_z1);
    cudaGetSymbolAddress((void**)&z2,   g_z2);
    cudaGetSymbolAddress((void**)&z3,   g_z3);
    cudaGetSymbolAddress((void**)&wT,   g_wT);
    cudaGetSymbolAddress((void**)&wPQT, g_wPQT);
    cudaGetSymbolAddress((void**)&emb16, g_emb16);
    cudaGetSymbolAddress((void**)&PQ,   g_PQ);
    cudaGetSymbolAddress((void**)&zeroB, g_zeroBias);
    cudaGetSymbolAddress((void**)&hb1p, g_hb1p);
    cudaGetSymbolAddress((void**)&g_skP_ptr, g_skP);

    cudaFuncSetAttribute(gemm_mma<ACT_RELU>,
                         cudaFuncAttributeMaxDynamicSharedMemorySize, GSMEM128);
    cudaFuncSetAttribute(gemm_mma<ACT_TANH>,
                         cudaFuncAttributeMaxDynamicSharedMemorySize, GSMEM128);
    cudaFuncSetAttribute(gemm_mma<ACT_NONE>,
                         cudaFuncAttributeMaxDynamicSharedMemorySize, GSMEM128);
    cudaFuncSetAttribute(gemm_mma_sk,
                         cudaFuncAttributeMaxDynamicSharedMemorySize, GSMEM128);

    // 0) prep: emb -> fp16 (padded table), head bias fold, weight transposes
    emb_cvt_kernel<<<NENT_, E_ / 4>>>(ent, emb16);
    headbias_kernel<<<4, 128>>>(th, h1, hb1, hb1p);
    {
        TransJobs jobs;
        const float* Ws[9]  = {w1, w1 + (size_t)512 * 2048, w1, w2, o1, o2,
                               h1 + (size_t)512 * 512, h2, h3};
        __half* Wts[9] = {wPQT, wPQT + (size_t)2048 * 512,
                          wT + W1T_OFF, wT + W2T_OFF, wT + O1T_OFF, wT + O2T_OFF,
                          wT + H1T_OFF, wT + H2T_OFF, wT + H3T_OFF};
        const int Ks[9] = {512, 512, 2 * E_, 4 * E_, E_, 4 * E_, 2 * E_, E_, E_ / 2};
        const int Ns[9] = {4 * E_, 4 * E_, 4 * E_, E_, 4 * E_, E_, E_, E_ / 2, E_ / 4};
        int acc = 0;
        for (int j = 0; j < 9; j++) {
            jobs.W[j] = Ws[j]; jobs.Wt[j] = Wts[j];
            jobs.K[j] = Ks[j]; jobs.N[j] = Ns[j];
            jobs.ofs[j] = acc;
            acc += (Ns[j] / 64) * (Ks[j] / 64);
        }
        jobs.ofs[9] = acc;
        transpose_all<<<acc, dim3(32, 8)>>>(jobs);
    }

    // 1) PQ = emb16 @ [w1_top | w1_bot]  : [2048, 4096], no bias/act
    {
        dim3 g(4096 / 128, NENTP / 128);
        gemm_mma<ACT_NONE><<<g, 128, GSMEM128>>>(emb16, wPQT, zeroB, PQ,
                                                 NENTP, 4096, 512);
    }

    // 2) level-1 H = relu(P[ia] + Q[ib] + b1) : [32768, 2048]
    {
        const int rows = B_ * NT_ * (NL_ / 2);    // 32768
        gaddrelu_kernel<<<rows, 256>>>(leaf, PQ, b1, H);
        launch_gemm(ACT_RELU, H, wT + W2T_OFF, b2, bufB, rows, E_, 4 * E_);
    }

    // 3) tree reduction levels 2..6
    __half* in  = bufB;
    __half* out = bufA;
    int n = NL_ / 2;
    while (n > 1) {
        const int rows = B_ * NT_ * (n / 2);
        launch_gemm(ACT_RELU, in, wT + W1T_OFF, b1, H, rows, 4 * E_, 2 * E_);
        launch_gemm(ACT_RELU, H, wT + W2T_OFF, b2, out, rows, E_, 4 * E_);
        __half* tp = in; in = out; out = tp;
        n >>= 1;
    }
    // after 5 swaps starting from in=bufB: in=bufA (root)

    // 4) one2one
    {
        const int rows = B_ * NT_;
        launch_gemm(ACT_RELU, in, wT + O1T_OFF, ob1, H, rows, 4 * E_, E_);
        launch_gemm(ACT_TANH, H, wT + O2T_OFF, ob2, out, rows, E_, 4 * E_);
    }
    // root2 in `out` = bufB : [512, 1024]

    // 5) head (th folded into hb1p; K = 1024)
    launch_gemm(ACT_RELU, out, wT + H1T_OFF, hb1p, z1, B_, E_, NT_ * E_);
    launch_gemm(ACT_RELU, z1, wT + H2T_OFF, hb2, z2, B_, E_ / 2, E_);
    launch_gemm(ACT_RELU, z2, wT + H3T_OFF, hb3, z3, B_, E_ / 4, E_ / 2);

    // 6) final dot + sigmoid
    final_kernel<<<(B_ * 32 + 255) / 256, 256>>>(z3, h4, hb4, (float*)d_out);
}

// round 17
// speedup vs baseline: 1.0514x; 1.0019x over previous
#include <cuda_runtime.h>
#include <cuda_fp16.h>
#include <math.h>
#include <stdint.h>

// ===========================================================================
// LogicRecursiveNN on GB300 (plain sm_103 target -> mma.sync path).
// Single-pass fp16 GEMMs, f32 accumulate.  (R16 structure, 5-stage pipeline.)
// ALGEBRAIC OPTS:
//  - L1-G1 factored through the 2000-entry dictionary: PQ = emb @ [w1t|w1b];
//    H = relu(P[ia] + Q[ib] + b1) via a gather-add-relu kernel.
//  - Head: th batch-constant -> th @ h1_top folded into bias.
// Hot GEMMs: 128x128 CTA, 128 thr, warp tile 64x64, KC=32, 5 stg, 2 CTAs/SM.
// Tail GEMMs (< 1 wave): split-K (S<=8) + reduce.
// ===========================================================================

#define B_    512
#define NT_   2
#define NL_   64
#define E_    512
#define T_    512

#define SB_   ((size_t)B_ * NT_ * NL_ * E_ / 2)
#define SH_   ((size_t)B_ * NT_ * (NL_/2) * 4 * E_)
#define SZ1_  ((size_t)B_ * E_)
#define SZ2_  ((size_t)B_ * (E_/2))
#define SZ3_  ((size_t)B_ * (E_/4))
#define NENT_ 2000
#define NENTP 2048

__device__ __half g_bufA[SB_];
__device__ __half g_bufB[SB_];
__device__ __half g_bufH[SH_];
__device__ __half g_z1[SZ1_];
__device__ __half g_z2[SZ2_];
__device__ __half g_z3[SZ3_];
__device__ __half g_wT[6193152];
__device__ __half g_wPQT[(size_t)4096 * 512];
__device__ __half g_emb16[(size_t)NENTP * E_];
__device__ __half g_PQ[(size_t)NENTP * 4096];
__device__ float  g_skP[8388608];
__device__ float  g_zeroBias[4096];
__device__ float  g_hb1p[E_];

#define W1T_OFF  0          // [2048,1024]
#define W2T_OFF  2097152    // [512,2048]
#define O1T_OFF  3145728    // [2048,512]
#define O2T_OFF  4194304    // [512,2048]
#define H1T_OFF  5242880    // [512,1024]  (h1 bottom only)
#define H2T_OFF  6029312    // [256,512]
#define H3T_OFF  6160384    // [128,256]

// ---------------------------------------------------------------------------
// helpers
// ---------------------------------------------------------------------------
__device__ __forceinline__ uint32_t smem_u32(const void* p) {
    uint32_t a;
    asm("{ .reg .u64 t; cvta.to.shared.u64 t, %1; cvt.u32.u64 %0, t; }"
        : "=r"(a) : "l"(p));
    return a;
}
__device__ __forceinline__ void cp16(uint32_t dst, const void* src) {
    asm volatile("cp.async.cg.shared.global [%0], [%1], 16;"
                 :: "r"(dst), "l"(src) : "memory");
}
__device__ __forceinline__ void cp_commit() {
    asm volatile("cp.async.commit_group;" ::: "memory");
}
template <int N>
__device__ __forceinline__ void cp_wait() {
    asm volatile("cp.async.wait_group %0;" :: "n"(N) : "memory");
}
__device__ __forceinline__ void ldm_x4(uint32_t* r, uint32_t addr) {
    asm volatile("ldmatrix.sync.aligned.m8n8.x4.shared.b16 {%0,%1,%2,%3}, [%4];"
                 : "=r"(r[0]), "=r"(r[1]), "=r"(r[2]), "=r"(r[3]) : "r"(addr));
}
__device__ __forceinline__ void mma_f16(float* c, const uint32_t* a, const uint32_t* b) {
    asm volatile(
        "mma.sync.aligned.m16n8k16.row.col.f32.f16.f16.f32 "
        "{%0,%1,%2,%3}, {%4,%5,%6,%7}, {%8,%9}, {%0,%1,%2,%3};"
        : "+f"(c[0]), "+f"(c[1]), "+f"(c[2]), "+f"(c[3])
        : "r"(a[0]), "r"(a[1]), "r"(a[2]), "r"(a[3]), "r"(b[0]), "r"(b[1]));
}

#define ACT_RELU 0
#define ACT_TANH 1
#define ACT_NONE 2
template <int ACT>
__device__ __forceinline__ float apply_act(float x) {
    if (ACT == ACT_RELU) return fmaxf(x, 0.0f);
    if (ACT == ACT_TANH) return tanhf(x);
    return x;
}

// ---------------------------------------------------------------------------
// small kernels
// ---------------------------------------------------------------------------
__global__ void emb_cvt_kernel(const float* __restrict__ emb,
                               __half* __restrict__ out)
{
    const size_t o = (size_t)blockIdx.x * E_ + threadIdx.x * 4;
    const float4 v = *(const float4*)(emb + o);
    __half h[4];
    h[0] = __float2half_rn(v.x); h[1] = __float2half_rn(v.y);
    h[2] = __float2half_rn(v.z); h[3] = __float2half_rn(v.w);
    *(uint2*)(out + o) = *(uint2*)h;
}

struct TransJobs {
    const float* W[9];
    __half* Wt[9];
    int K[9], N[9];
    int ofs[10];
};

// 64x64 tiles, block (32,8); all K,N are multiples of 64.
__global__ void transpose_all(TransJobs jobs)
{
    __shared__ float t[64][65];
    int j = 0;
#pragma unroll
    for (int q = 1; q < 9; q++) if ((int)blockIdx.x >= jobs.ofs[q]) j = q;
    const int tile = blockIdx.x - jobs.ofs[j];
    const int K = jobs.K[j], N = jobs.N[j];
    const int tilesX = N / 64;
    const int bx = (tile % tilesX) * 64;
    const int by = (tile / tilesX) * 64;
    const float* W = jobs.W[j];
    __half* Wt = jobs.Wt[j];
    const int tx = threadIdx.x;

    for (int i = threadIdx.y; i < 64; i += 8) {
        t[i][tx]      = W[(size_t)(by + i) * N + bx + tx];
        t[i][tx + 32] = W[(size_t)(by + i) * N + bx + tx + 32];
    }
    __syncthreads();
    for (int i = threadIdx.y; i < 64; i += 8) {
        Wt[(size_t)(bx + i) * K + by + tx]      = __float2half_rn(t[tx][i]);
        Wt[(size_t)(bx + i) * K + by + tx + 32] = __float2half_rn(t[tx + 32][i]);
    }
}

// H[row] = relu(PQ[ia, 0:2048] + PQ[ib, 2048:4096] + b1)
__global__ void gaddrelu_kernel(const int* __restrict__ idx,
                                const __half* __restrict__ PQ,
                                const float* __restrict__ b1,
                                __half* __restrict__ H)
{
    const int row = blockIdx.x;
    const int ia = __ldg(idx + 2 * row);
    const int ib = __ldg(idx + 2 * row + 1);
    const int off = threadIdx.x * 8;
    const uint4 pv = *(const uint4*)(PQ + (size_t)ia * 4096 + off);
    const uint4 qv = *(const uint4*)(PQ + (size_t)ib * 4096 + 2048 + off);
    const __half2* ph = (const __half2*)&pv;
    const __half2* qh = (const __half2*)&qv;
    const float4 b0 = *(const float4*)(b1 + off);
    const float4 b4 = *(const float4*)(b1 + off + 4);
    const float bb[8] = {b0.x, b0.y, b0.z, b0.w, b4.x, b4.y, b4.z, b4.w};
    __half hres[8];
#pragma unroll
    for (int i = 0; i < 4; i++) {
        const float2 pf = __half22float2(ph[i]);
        const float2 qf = __half22float2(qh[i]);
        hres[2 * i]     = __float2half_rn(fmaxf(pf.x + qf.x + bb[2 * i], 0.0f));
        hres[2 * i + 1] = __float2half_rn(fmaxf(pf.y + qf.y + bb[2 * i + 1], 0.0f));
    }
    *(uint4*)(H + (size_t)row * 2048 + off) = *(uint4*)hres;
}

// hb1'[n] = hb1[n] + sum_t th[t] * h1[t, n]
__global__ void headbias_kernel(const float* __restrict__ th,
                                const float* __restrict__ h1,
                                const float* __restrict__ hb1,
                                float* __restrict__ outb)
{
    const int n = blockIdx.x * blockDim.x + threadIdx.x;
    float s = hb1[n];
    for (int t = 0; t < T_; t++)
        s = fmaf(th[t], h1[(size_t)t * E_ + n], s);
    outb[n] = s;
}

__global__ void final_kernel(const __half* __restrict__ z3,
                             const float* __restrict__ w,
                             const float* __restrict__ b0,
                             float* __restrict__ out)
{
    const int warp = (blockIdx.x * blockDim.x + threadIdx.x) >> 5;
    const int lane = threadIdx.x & 31;
    if (warp >= B_) return;
    const size_t base = (size_t)warp * 128;
    float s = 0.0f;
#pragma unroll
    for (int i = lane; i < 128; i += 32)
        s = fmaf(__half2float(z3[base + i]), w[i], s);
#pragma unroll
    for (int o = 16; o > 0; o >>= 1) s += __shfl_down_sync(0xFFFFFFFFu, s, o);
    if (lane == 0) {
        const float x = s + b0[0];
        out[warp] = 1.0f / (1.0f + expf(-x));
    }
}

// ---------------------------------------------------------------------------
// GEMM tiling constants
// ---------------------------------------------------------------------------
#define KC       32
#define PITCH    80
#define STG      5
#define TILE128  (128 * PITCH)
#define STAGE128 (2 * TILE128)
#define GSMEM128 (STG * STAGE128)            // 102400 (x2 CTAs = 200 KB/SM)

// ---------------------------------------------------------------------------
// gemm_mma: full-K kernel, bias+act epilogue, fp16 out.
// ---------------------------------------------------------------------------
template <int ACT>
__global__ void __launch_bounds__(128, 2)
gemm_mma(const __half* __restrict__ A,
         const __half* __restrict__ Bt,
         const float* __restrict__ bias,
         __half* __restrict__ C,
         int M, int N, int K)
{
    extern __shared__ char smem[];
    const uint32_t sb = smem_u32(smem);
    const int tid = threadIdx.x;
    const int wid = tid >> 5;
    const int lane = tid & 31;
    const int wm = wid >> 1;
    const int wn = wid & 1;

    const size_t row0 = (size_t)blockIdx.y * 128;
    const size_t col0 = (size_t)blockIdx.x * 128;
    const __half* Ag = A + row0 * K;
    const __half* Bg = Bt + col0 * K;

    const int seg = tid & 3;
    const int rowc = tid >> 2;

    const int nk = K / KC;

#pragma unroll
    for (int c = 0; c < STG - 1; c++) {
        if (c < nk) {
            const uint32_t st = sb + c * STAGE128;
            const int k0 = c * KC;
#pragma unroll
            for (int h = 0; h < 4; h++) {
                const int r = rowc + h * 32;
                const size_t go = (size_t)r * K + k0 + seg * 8;
                const uint32_t so = r * PITCH + seg * 16;
                cp16(st + so, Ag + go);
                cp16(st + TILE128 + so, Bg + go);
            }
        }
        cp_commit();
    }

    float acc[4][8][4];
#pragma unroll
    for (int i = 0; i < 4; i++)
#pragma unroll
        for (int j = 0; j < 8; j++)
#pragma unroll
            for (int k = 0; k < 4; k++) acc[i][j][k] = 0.0f;

    const uint32_t aoff = (uint32_t)((wm * 64 + (lane & 15)) * PITCH + (lane >> 4) * 16);
    const uint32_t boff = (uint32_t)((wn * 64 + (lane & 7) + ((lane >> 4) << 3)) * PITCH
                                     + ((lane >> 3) & 1) * 16);

    for (int i = 0; i < nk; i++) {
        cp_wait<STG - 2>();
        __syncthreads();

        const uint32_t st = sb + (i % STG) * STAGE128;
        const uint32_t aB = st + aoff;
        const uint32_t bB = st + TILE128 + boff;

        uint32_t af[2][4][4], bf[2][4][4];
#pragma unroll
        for (int ks = 0; ks < 2; ks++) {
#pragma unroll
            for (int mt = 0; mt < 4; mt++)
                ldm_x4(af[ks][mt], aB + mt * (16 * PITCH) + ks * 32);
#pragma unroll
            for (int nt2 = 0; nt2 < 4; nt2++)
                ldm_x4(bf[ks][nt2], bB + nt2 * (16 * PITCH) + ks * 32);
        }
#pragma unroll
        for (int ks = 0; ks < 2; ks++)
#pragma unroll
            for (int mt = 0; mt < 4; mt++)
#pragma unroll
                for (int nt2 = 0; nt2 < 4; nt2++) {
                    mma_f16(acc[mt][2 * nt2 + 0], af[ks][mt], &bf[ks][nt2][0]);
                    mma_f16(acc[mt][2 * nt2 + 1], af[ks][mt], &bf[ks][nt2][2]);
                }

        const int c = i + STG - 1;
        if (c < nk) {
            const uint32_t stw = sb + (c % STG) * STAGE128;
            const int k0 = c * KC;
#pragma unroll
            for (int h = 0; h < 4; h++) {
                const int r = rowc + h * 32;
                const size_t go = (size_t)r * K + k0 + seg * 8;
                const uint32_t so = r * PITCH + seg * 16;
                cp16(stw + so, Ag + go);
                cp16(stw + TILE128 + so, Bg + go);
            }
        }
        cp_commit();
    }

    const int lr = lane >> 2;
    const int lc = (lane & 3) * 2;
#pragma unroll
    for (int mt = 0; mt < 4; mt++) {
#pragma unroll
        for (int nt = 0; nt < 8; nt++) {
            const size_t r0 = row0 + wm * 64 + mt * 16 + lr;
            const size_t cc = col0 + wn * 64 + nt * 8 + lc;
            const float bx = __ldg(bias + cc);
            const float by = __ldg(bias + cc + 1);
#pragma unroll
            for (int hh = 0; hh < 2; hh++) {
                const size_t r = r0 + hh * 8;
                __half hp[2];
                hp[0] = __float2half_rn(apply_act<ACT>(acc[mt][nt][hh * 2 + 0] + bx));
                hp[1] = __float2half_rn(apply_act<ACT>(acc[mt][nt][hh * 2 + 1] + by));
                *(uint32_t*)(C + r * N + cc) = *(uint32_t*)hp;
            }
        }
    }
}

// ---------------------------------------------------------------------------
// gemm_mma_sk: split-K kernel -> raw f32 partials.
// ---------------------------------------------------------------------------
__global__ void __launch_bounds__(128, 2)
gemm_mma_sk(const __half* __restrict__ A,
            const __half* __restrict__ Bt,
            float* __restrict__ P,
            int M, int N, int K, int klen)
{
    extern __shared__ char smem[];
    const uint32_t sb = smem_u32(smem);
    const int tid = threadIdx.x;
    const int wid = tid >> 5;
    const int lane = tid & 31;
    const int wm = wid >> 1;
    const int wn = wid & 1;

    const size_t row0 = (size_t)blockIdx.y * 128;
    const size_t col0 = (size_t)blockIdx.x * 128;
    const int kbase = blockIdx.z * klen;
    const __half* Ag = A + row0 * K + kbase;
    const __half* Bg = Bt + col0 * K + kbase;
    float* Pg = P + (size_t)blockIdx.z * M * N;

    const int seg = tid & 3;
    const int rowc = tid >> 2;

    const int nk = klen / KC;

#pragma unroll
    for (int c = 0; c < STG - 1; c++) {
        if (c < nk) {
            const uint32_t st = sb + c * STAGE128;
            const int k0 = c * KC;
#pragma unroll
            for (int h = 0; h < 4; h++) {
                const int r = rowc + h * 32;
                const size_t go = (size_t)r * K + k0 + seg * 8;
                const uint32_t so = r * PITCH + seg * 16;
                cp16(st + so, Ag + go);
                cp16(st + TILE128 + so, Bg + go);
            }
        }
        cp_commit();
    }

    float acc[4][8][4];
#pragma unroll
    for (int i = 0; i < 4; i++)
#pragma unroll
        for (int j = 0; j < 8; j++)
#pragma unroll
            for (int k = 0; k < 4; k++) acc[i][j][k] = 0.0f;

    const uint32_t aoff = (uint32_t)((wm * 64 + (lane & 15)) * PITCH + (lane >> 4) * 16);
    const uint32_t boff = (uint32_t)((wn * 64 + (lane & 7) + ((lane >> 4) << 3)) * PITCH
                                     + ((lane >> 3) & 1) * 16);

    for (int i = 0; i < nk; i++) {
        cp_wait<STG - 2>();
        __syncthreads();

        const uint32_t st = sb + (i % STG) * STAGE128;
        const uint32_t aB = st + aoff;
        const uint32_t bB = st + TILE128 + boff;

        uint32_t af[2][4][4], bf[2][4][4];
#pragma unroll
        for (int ks = 0; ks < 2; ks++) {
#pragma unroll
            for (int mt = 0; mt < 4; mt++)
                ldm_x4(af[ks][mt], aB + mt * (16 * PITCH) + ks * 32);
#pragma unroll
            for (int nt2 = 0; nt2 < 4; nt2++)
                ldm_x4(bf[ks][nt2], bB + nt2 * (16 * PITCH) + ks * 32);
        }
#pragma unroll
        for (int ks = 0; ks < 2; ks++)
#pragma unroll
            for (int mt = 0; mt < 4; mt++)
#pragma unroll
                for (int nt2 = 0; nt2 < 4; nt2++) {
                    mma_f16(acc[mt][2 * nt2 + 0], af[ks][mt], &bf[ks][nt2][0]);
                    mma_f16(acc[mt][2 * nt2 + 1], af[ks][mt], &bf[ks][nt2][2]);
                }

        const int c = i + STG - 1;
        if (c < nk) {
            const uint32_t stw = sb + (c % STG) * STAGE128;
            const int k0 = c * KC;
#pragma unroll
            for (int h = 0; h < 4; h++) {
                const int r = rowc + h * 32;
                const size_t go = (size_t)r * K + k0 + seg * 8;
                const uint32_t so = r * PITCH + seg * 16;
                cp16(stw + so, Ag + go);
                cp16(stw + TILE128 + so, Bg + go);
            }
        }
        cp_commit();
    }

    const int lr = lane >> 2;
    const int lc = (lane & 3) * 2;
#pragma unroll
    for (int mt = 0; mt < 4; mt++) {
#pragma unroll
        for (int nt = 0; nt < 8; nt++) {
            const size_t r0 = row0 + wm * 64 + mt * 16 + lr;
            const size_t cc = col0 + wn * 64 + nt * 8 + lc;
#pragma unroll
            for (int hh = 0; hh < 2; hh++) {
                const size_t r = r0 + hh * 8;
                float2 v;
                v.x = acc[mt][nt][hh * 2 + 0];
                v.y = acc[mt][nt][hh * 2 + 1];
                *(float2*)(Pg + r * N + cc) = v;
            }
        }
    }
}

template <int ACT>
__global__ void reduce_sk(const float* __restrict__ P,
                          const float* __restrict__ bias,
                          __half* __restrict__ C,
                          int MN, int N, int S)
{
    const int idx = (blockIdx.x * blockDim.x + threadIdx.x) * 4;
    if (idx >= MN) return;
    float4 a = *(const float4*)(P + idx);
    for (int s = 1; s < S; s++) {
        const float4 b = *(const float4*)(P + (size_t)s * MN + idx);
        a.x += b.x; a.y += b.y; a.z += b.z; a.w += b.w;
    }
    const int col = idx % N;
    const float4 bv = *(const float4*)(bias + col);
    __half h[4];
    h[0] = __float2half_rn(apply_act<ACT>(a.x + bv.x));
    h[1] = __float2half_rn(apply_act<ACT>(a.y + bv.y));
    h[2] = __float2half_rn(apply_act<ACT>(a.z + bv.z));
    h[3] = __float2half_rn(apply_act<ACT>(a.w + bv.w));
    *(uint2*)(C + idx) = *(uint2*)h;
}

// ---------------------------------------------------------------------------
// launch
// ---------------------------------------------------------------------------
static float* g_skP_ptr = nullptr;

static void launch_gemm(int act, const __half* A, const __half* Bt,
                        const float* bias, __half* C, int M, int N, int K)
{
    const int ctas = (M / 128) * (N / 128);
    const int iters = K / KC;

    int S = 1;
    if (ctas < 296 && iters >= 4) {
        while (S < 8 && ctas * (S * 2) <= 592 &&
               (iters % (S * 2)) == 0 && (iters / (S * 2)) >= 2)
            S *= 2;
    }

    if (S > 1) {
        dim3 g(N / 128, M / 128, S);
        gemm_mma_sk<<<g, 128, GSMEM128>>>(A, Bt, g_skP_ptr, M, N, K, K / S);
        const int MN = M * N;
        const int thr = 256;
        const int blocks = (MN / 4 + thr - 1) / thr;
        if (act == ACT_RELU)
            reduce_sk<ACT_RELU><<<blocks, thr>>>(g_skP_ptr, bias, C, MN, N, S);
        else
            reduce_sk<ACT_TANH><<<blocks, thr>>>(g_skP_ptr, bias, C, MN, N, S);
    } else {
        dim3 g(N / 128, M / 128);
        if (act == ACT_RELU)
            gemm_mma<ACT_RELU><<<g, 128, GSMEM128>>>(A, Bt, bias, C, M, N, K);
        else
            gemm_mma<ACT_TANH><<<g, 128, GSMEM128>>>(A, Bt, bias, C, M, N, K);
    }
}

extern "C" void kernel_launch(void* const* d_in, const int* in_sizes, int n_in,
                              void* d_out, int out_size)
{
    const int*   leaf = (const int*)  d_in[0];
    const float* ent  = (const float*)d_in[1];
    const float* th   = (const float*)d_in[2];
    const float* w1   = (const float*)d_in[3];
    const float* b1   = (const float*)d_in[4];
    const float* w2   = (const float*)d_in[5];
    const float* b2   = (const float*)d_in[6];
    const float* o1   = (const float*)d_in[7];
    const float* ob1  = (const float*)d_in[8];
    const float* o2   = (const float*)d_in[9];
    const float* ob2  = (const float*)d_in[10];
    const float* h1   = (const float*)d_in[11];
    const float* hb1  = (const float*)d_in[12];
    const float* h2   = (const float*)d_in[13];
    const float* hb2  = (const float*)d_in[14];
    const float* h3   = (const float*)d_in[15];
    const float* hb3  = (const float*)d_in[16];
    const float* h4   = (const float*)d_in[17];
    const float* hb4  = (const float*)d_in[18];

    __half *bufA, *bufB, *H, *z1, *z2, *z3, *wT, *wPQT, *emb16, *PQ;
    float *zeroB, *hb1p;
    cudaGetSymbolAddress((void**)&bufA, g_bufA);
    cudaGetSymbolAddress((void**)&bufB, g_bufB);
    cudaGetSymbolAddress((void**)&H,    g_bufH);
    cudaGetSymbolAddress((void**)&z1,   g_z1);
    cudaGetSymbolAddress((void**)&z2,   g_z2);
    cudaGetSymbolAddress((void**)&z3,   g_z3);
    cudaGetSymbolAddress((void**)&wT,   g_wT);
    cudaGetSymbolAddress((void**)&wPQT, g_wPQT);
    cudaGetSymbolAddress((void**)&emb16, g_emb16);
    cudaGetSymbolAddress((void**)&PQ,   g_PQ);
    cudaGetSymbolAddress((void**)&zeroB, g_zeroBias);
    cudaGetSymbolAddress((void**)&hb1p, g_hb1p);
    cudaGetSymbolAddress((void**)&g_skP_ptr, g_skP);

    cudaFuncSetAttribute(gemm_mma<ACT_RELU>,
                         cudaFuncAttributeMaxDynamicSharedMemorySize, GSMEM128);
    cudaFuncSetAttribute(gemm_mma<ACT_TANH>,
                         cudaFuncAttributeMaxDynamicSharedMemorySize, GSMEM128);
    cudaFuncSetAttribute(gemm_mma<ACT_NONE>,
                         cudaFuncAttributeMaxDynamicSharedMemorySize, GSMEM128);
    cudaFuncSetAttribute(gemm_mma_sk,
                         cudaFuncAttributeMaxDynamicSharedMemorySize, GSMEM128);

    // 0) prep: emb -> fp16 (padded table), head bias fold, weight transposes
    emb_cvt_kernel<<<NENT_, E_ / 4>>>(ent, emb16);
    headbias_kernel<<<4, 128>>>(th, h1, hb1, hb1p);
    {
        TransJobs jobs;
        const float* Ws[9]  = {w1, w1 + (size_t)512 * 2048, w1, w2, o1, o2,
                               h1 + (size_t)512 * 512, h2, h3};
        __half* Wts[9] = {wPQT, wPQT + (size_t)2048 * 512,
                          wT + W1T_OFF, wT + W2T_OFF, wT + O1T_OFF, wT + O2T_OFF,
                          wT + H1T_OFF, wT + H2T_OFF, wT + H3T_OFF};
        const int Ks[9] = {512, 512, 2 * E_, 4 * E_, E_, 4 * E_, 2 * E_, E_, E_ / 2};
        const int Ns[9] = {4 * E_, 4 * E_, 4 * E_, E_, 4 * E_, E_, E_, E_ / 2, E_ / 4};
        int acc = 0;
        for (int j = 0; j < 9; j++) {
            jobs.W[j] = Ws[j]; jobs.Wt[j] = Wts[j];
            jobs.K[j] = Ks[j]; jobs.N[j] = Ns[j];
            jobs.ofs[j] = acc;
            acc += (Ns[j] / 64) * (Ks[j] / 64);
        }
        jobs.ofs[9] = acc;
        transpose_all<<<acc, dim3(32, 8)>>>(jobs);
    }

    // 1) PQ = emb16 @ [w1_top | w1_bot]  : [2048, 4096], no bias/act
    {
        dim3 g(4096 / 128, NENTP / 128);
        gemm_mma<ACT_NONE><<<g, 128, GSMEM128>>>(emb16, wPQT, zeroB, PQ,
                                                 NENTP, 4096, 512);
    }

    // 2) level-1 H = relu(P[ia] + Q[ib] + b1) : [32768, 2048]
    {
        const int rows = B_ * NT_ * (NL_ / 2);    // 32768
        gaddrelu_kernel<<<rows, 256>>>(leaf, PQ, b1, H);
        launch_gemm(ACT_RELU, H, wT + W2T_OFF, b2, bufB, rows, E_, 4 * E_);
    }

    // 3) tree reduction levels 2..6
    __half* in  = bufB;
    __half* out = bufA;
    int n = NL_ / 2;
    while (n > 1) {
        const int rows = B_ * NT_ * (n / 2);
        launch_gemm(ACT_RELU, in, wT + W1T_OFF, b1, H, rows, 4 * E_, 2 * E_);
        launch_gemm(ACT_RELU, H, wT + W2T_OFF, b2, out, rows, E_, 4 * E_);
        __half* tp = in; in = out; out = tp;
        n >>= 1;
    }
    // after 5 swaps starting from in=bufB: in=bufA (root)

    // 4) one2one
    {
        const int rows = B_ * NT_;
        launch_gemm(ACT_RELU, in, wT + O1T_OFF, ob1, H, rows, 4 * E_, E_);
        launch_gemm(ACT_TANH, H, wT + O2T_OFF, ob2, out, rows, E_, 4 * E_);
    }
    // root2 in `out` = bufB : [512, 1024]

    // 5) head (th folded into hb1p; K = 1024)
    launch_gemm(ACT_RELU, out, wT + H1T_OFF, hb1p, z1, B_, E_, NT_ * E_);
    launch_gemm(ACT_RELU, z1, wT + H2T_OFF, hb2, z2, B_, E_ / 2, E_);
    launch_gemm(ACT_RELU, z2, wT + H3T_OFF, hb3, z3, B_, E_ / 4, E_ / 2);

    // 6) final dot + sigmoid
    final_kernel<<<(B_ * 32 + 255) / 256, 256>>>(z3, h4, hb4, (float*)d_out);
}